// round 1
// baseline (speedup 1.0000x reference)
#include <cuda_runtime.h>
#include <math.h>

#define S_LEN 2048
#define HID   2048
#define NH    32
#define NKV   8
#define HD    64
#define QKV_N 3072          // 2048 q + 512 k + 512 v
#define CTX_N 2048
#define K_OFF 2048
#define V_OFF 2560

// scratch (no cudaMalloc allowed)
__device__ float g_qkv[S_LEN * QKV_N];   // 25.2 MB
__device__ float g_ctx[S_LEN * CTX_N];   // 16.8 MB

// ---------------------------------------------------------------------------
// C[m][n] = sum_k A[m][k] * B[n][k]   (A: MxK row-major, B: NxK row-major)
// 128x128 tile, BK=16, 256 threads, 8x8 per-thread micro-tile.
// ---------------------------------------------------------------------------
__global__ __launch_bounds__(256) void gemm_tn(const float* __restrict__ A,
                                               const float* __restrict__ B,
                                               float* __restrict__ C,
                                               int M, int N, int K) {
    __shared__ float As[16][132];
    __shared__ float Bs[16][132];
    const int tid = threadIdx.x;
    const int m0 = blockIdx.y * 128;
    const int n0 = blockIdx.x * 128;
    const int tx = tid & 15;        // 0..15 -> n micro
    const int ty = tid >> 4;        // 0..15 -> m micro
    const int lr = tid >> 2;        // 0..63 load row
    const int lc = (tid & 3) << 2;  // 0,4,8,12 load col (floats)

    float acc[8][8];
#pragma unroll
    for (int i = 0; i < 8; i++)
#pragma unroll
        for (int j = 0; j < 8; j++) acc[i][j] = 0.0f;

    const float* Ar0 = A + (long)(m0 + lr) * K + lc;
    const float* Ar1 = A + (long)(m0 + lr + 64) * K + lc;
    const float* Br0 = B + (long)(n0 + lr) * K + lc;
    const float* Br1 = B + (long)(n0 + lr + 64) * K + lc;

    for (int kk = 0; kk < K; kk += 16) {
        float4 a0 = *(const float4*)(Ar0 + kk);
        float4 a1 = *(const float4*)(Ar1 + kk);
        float4 b0 = *(const float4*)(Br0 + kk);
        float4 b1 = *(const float4*)(Br1 + kk);
        __syncthreads();
        As[lc + 0][lr] = a0.x; As[lc + 1][lr] = a0.y; As[lc + 2][lr] = a0.z; As[lc + 3][lr] = a0.w;
        As[lc + 0][lr + 64] = a1.x; As[lc + 1][lr + 64] = a1.y; As[lc + 2][lr + 64] = a1.z; As[lc + 3][lr + 64] = a1.w;
        Bs[lc + 0][lr] = b0.x; Bs[lc + 1][lr] = b0.y; Bs[lc + 2][lr] = b0.z; Bs[lc + 3][lr] = b0.w;
        Bs[lc + 0][lr + 64] = b1.x; Bs[lc + 1][lr + 64] = b1.y; Bs[lc + 2][lr + 64] = b1.z; Bs[lc + 3][lr + 64] = b1.w;
        __syncthreads();
#pragma unroll
        for (int k = 0; k < 16; k++) {
            float4 av0 = *(const float4*)&As[k][ty * 8];
            float4 av1 = *(const float4*)&As[k][ty * 8 + 4];
            float4 bv0 = *(const float4*)&Bs[k][tx * 8];
            float4 bv1 = *(const float4*)&Bs[k][tx * 8 + 4];
            float a[8] = {av0.x, av0.y, av0.z, av0.w, av1.x, av1.y, av1.z, av1.w};
            float b[8] = {bv0.x, bv0.y, bv0.z, bv0.w, bv1.x, bv1.y, bv1.z, bv1.w};
#pragma unroll
            for (int i = 0; i < 8; i++)
#pragma unroll
                for (int j = 0; j < 8; j++) acc[i][j] += a[i] * b[j];
        }
    }

#pragma unroll
    for (int i = 0; i < 8; i++) {
        float* crow = C + (long)(m0 + ty * 8 + i) * N + n0 + tx * 8;
        *(float4*)crow       = make_float4(acc[i][0], acc[i][1], acc[i][2], acc[i][3]);
        *(float4*)(crow + 4) = make_float4(acc[i][4], acc[i][5], acc[i][6], acc[i][7]);
    }
}

// ---------------------------------------------------------------------------
// RoPE (neox) in-place on q and k slices of qkv. positions = arange(S).
// grid: (S, NH+NKV), 32 threads: thread i rotates pair (i, i+32).
// ---------------------------------------------------------------------------
__global__ void rope_kernel(float* __restrict__ qkv) {
    const int s  = blockIdx.x;
    const int hh = blockIdx.y;                     // 0..NH+NKV-1
    const int i  = threadIdx.x;                    // 0..31
    const int base = (hh < NH) ? hh * HD : (K_OFF + (hh - NH) * HD);
    const float inv = powf(10000.0f, -(2.0f * (float)i) / 64.0f);
    const float ang = (float)s * inv;
    const float c = cosf(ang), sn = sinf(ang);
    float* row = qkv + (long)s * QKV_N + base;
    const float x1 = row[i];
    const float x2 = row[i + 32];
    row[i]      = x1 * c - x2 * sn;
    row[i + 32] = x2 * c + x1 * sn;
}

// ---------------------------------------------------------------------------
// Causal flash attention, fp32. 64x64 tiles, HD=64, 128 threads.
// Thread (ty=tid/8, tx=tid%8) owns rows ty*4..+3, cols tx*8..+7 of the tile.
// Row reductions: shfl_xor over tx bits (1,2,4).
// ---------------------------------------------------------------------------
#define FA_STRIDE 68
#define FA_SMEM   (4 * 64 * FA_STRIDE * 4)

__global__ __launch_bounds__(128) void flash_attn(const float* __restrict__ qkv,
                                                  float* __restrict__ ctx) {
    extern __shared__ float sm[];
    float (*Qs)[FA_STRIDE] = (float(*)[FA_STRIDE])sm;
    float (*Ks)[FA_STRIDE] = (float(*)[FA_STRIDE])(sm + 64 * FA_STRIDE);
    float (*Vs)[FA_STRIDE] = (float(*)[FA_STRIDE])(sm + 2 * 64 * FA_STRIDE);
    float (*Ps)[FA_STRIDE] = (float(*)[FA_STRIDE])(sm + 3 * 64 * FA_STRIDE);

    const int qi = blockIdx.x;
    const int h  = blockIdx.y;
    const int kvh = h >> 2;           // g = NH/NKV = 4
    const int tid = threadIdx.x;
    const int tx = tid & 7;
    const int ty = tid >> 3;
    const int q0 = qi * 64;

    // load Q tile [64][64]
#pragma unroll
    for (int it = 0; it < 8; ++it) {
        int f = tid + it * 128;
        int r = f >> 4;
        int c = (f & 15) * 4;
        *(float4*)&Qs[r][c] = *(const float4*)&qkv[(long)(q0 + r) * QKV_N + h * HD + c];
    }

    float m_i[4], l_i[4], acc[4][8];
#pragma unroll
    for (int rr = 0; rr < 4; rr++) {
        m_i[rr] = -INFINITY;
        l_i[rr] = 0.0f;
#pragma unroll
        for (int cc = 0; cc < 8; cc++) acc[rr][cc] = 0.0f;
    }

    for (int j = 0; j <= qi; ++j) {
        __syncthreads();   // prev PV done reading Vs/Ps before overwrite
        const int k0 = j * 64;
#pragma unroll
        for (int it = 0; it < 8; ++it) {
            int f = tid + it * 128;
            int r = f >> 4;
            int c = (f & 15) * 4;
            *(float4*)&Ks[r][c] = *(const float4*)&qkv[(long)(k0 + r) * QKV_N + K_OFF + kvh * HD + c];
            *(float4*)&Vs[r][c] = *(const float4*)&qkv[(long)(k0 + r) * QKV_N + V_OFF + kvh * HD + c];
        }
        __syncthreads();

        // S = Q K^T  (4x8 per thread)
        float s[4][8];
#pragma unroll
        for (int rr = 0; rr < 4; rr++)
#pragma unroll
            for (int cc = 0; cc < 8; cc++) s[rr][cc] = 0.0f;

#pragma unroll
        for (int d = 0; d < 64; d += 4) {
            float4 q4[4], k4[8];
#pragma unroll
            for (int rr = 0; rr < 4; rr++) q4[rr] = *(const float4*)&Qs[ty * 4 + rr][d];
#pragma unroll
            for (int cc = 0; cc < 8; cc++) k4[cc] = *(const float4*)&Ks[tx * 8 + cc][d];
#pragma unroll
            for (int rr = 0; rr < 4; rr++)
#pragma unroll
                for (int cc = 0; cc < 8; cc++)
                    s[rr][cc] += q4[rr].x * k4[cc].x + q4[rr].y * k4[cc].y
                               + q4[rr].z * k4[cc].z + q4[rr].w * k4[cc].w;
        }

        const bool diag = (j == qi);
#pragma unroll
        for (int rr = 0; rr < 4; rr++)
#pragma unroll
            for (int cc = 0; cc < 8; cc++) {
                float v = s[rr][cc] * 0.125f;   // 1/sqrt(64)
                if (diag && (tx * 8 + cc > ty * 4 + rr)) v = -INFINITY;
                s[rr][cc] = v;
            }

        // online softmax per row
#pragma unroll
        for (int rr = 0; rr < 4; rr++) {
            float mx = s[rr][0];
#pragma unroll
            for (int cc = 1; cc < 8; cc++) mx = fmaxf(mx, s[rr][cc]);
            mx = fmaxf(mx, __shfl_xor_sync(0xffffffffu, mx, 1));
            mx = fmaxf(mx, __shfl_xor_sync(0xffffffffu, mx, 2));
            mx = fmaxf(mx, __shfl_xor_sync(0xffffffffu, mx, 4));
            const float mnew = fmaxf(m_i[rr], mx);
            const float alpha = __expf(m_i[rr] - mnew);
            m_i[rr] = mnew;
            float sum = 0.0f;
#pragma unroll
            for (int cc = 0; cc < 8; cc++) {
                float p = __expf(s[rr][cc] - mnew);
                s[rr][cc] = p;
                sum += p;
            }
            sum += __shfl_xor_sync(0xffffffffu, sum, 1);
            sum += __shfl_xor_sync(0xffffffffu, sum, 2);
            sum += __shfl_xor_sync(0xffffffffu, sum, 4);
            l_i[rr] = l_i[rr] * alpha + sum;
#pragma unroll
            for (int cc = 0; cc < 8; cc++) acc[rr][cc] *= alpha;
        }

        // stage P to shared
#pragma unroll
        for (int rr = 0; rr < 4; rr++) {
            *(float4*)&Ps[ty * 4 + rr][tx * 8]     = make_float4(s[rr][0], s[rr][1], s[rr][2], s[rr][3]);
            *(float4*)&Ps[ty * 4 + rr][tx * 8 + 4] = make_float4(s[rr][4], s[rr][5], s[rr][6], s[rr][7]);
        }
        __syncthreads();

        // O += P V
#pragma unroll
        for (int n4 = 0; n4 < 16; n4++) {
            float4 p4[4];
#pragma unroll
            for (int rr = 0; rr < 4; rr++) p4[rr] = *(const float4*)&Ps[ty * 4 + rr][n4 * 4];
#pragma unroll
            for (int nn = 0; nn < 4; nn++) {
                const float4 v0 = *(const float4*)&Vs[n4 * 4 + nn][tx * 8];
                const float4 v1 = *(const float4*)&Vs[n4 * 4 + nn][tx * 8 + 4];
#pragma unroll
                for (int rr = 0; rr < 4; rr++) {
                    const float p = (nn == 0) ? p4[rr].x : (nn == 1) ? p4[rr].y
                                  : (nn == 2) ? p4[rr].z : p4[rr].w;
                    acc[rr][0] += p * v0.x; acc[rr][1] += p * v0.y;
                    acc[rr][2] += p * v0.z; acc[rr][3] += p * v0.w;
                    acc[rr][4] += p * v1.x; acc[rr][5] += p * v1.y;
                    acc[rr][6] += p * v1.z; acc[rr][7] += p * v1.w;
                }
            }
        }
    }

    // epilogue: ctx[s][h*64 + d] = O / l
#pragma unroll
    for (int rr = 0; rr < 4; rr++) {
        const float inv = 1.0f / l_i[rr];
        float* crow = ctx + (long)(q0 + ty * 4 + rr) * CTX_N + h * HD + tx * 8;
        *(float4*)crow       = make_float4(acc[rr][0] * inv, acc[rr][1] * inv, acc[rr][2] * inv, acc[rr][3] * inv);
        *(float4*)(crow + 4) = make_float4(acc[rr][4] * inv, acc[rr][5] * inv, acc[rr][6] * inv, acc[rr][7] * inv);
    }
}

// ---------------------------------------------------------------------------
extern "C" void kernel_launch(void* const* d_in, const int* in_sizes, int n_in,
                              void* d_out, int out_size) {
    // inputs (setup_inputs order): position_ids, hidden_states, w_qkv, w_o
    const float* hidden = (const float*)d_in[1];
    const float* w_qkv  = (const float*)d_in[2];
    const float* w_o    = (const float*)d_in[3];
    float* out = (float*)d_out;

    float* qkv;
    float* ctx;
    cudaGetSymbolAddress((void**)&qkv, g_qkv);
    cudaGetSymbolAddress((void**)&ctx, g_ctx);

    // 1) fused QKV projection: [2048,2048] x [3072,2048]^T -> [2048,3072]
    {
        dim3 grid(QKV_N / 128, S_LEN / 128);
        gemm_tn<<<grid, 256>>>(hidden, w_qkv, qkv, S_LEN, QKV_N, HID);
    }
    // 2) RoPE on q,k
    {
        dim3 grid(S_LEN, NH + NKV);
        rope_kernel<<<grid, 32>>>(qkv);
    }
    // 3) causal flash attention (GQA)
    {
        cudaFuncSetAttribute(flash_attn, cudaFuncAttributeMaxDynamicSharedMemorySize, FA_SMEM);
        dim3 grid(S_LEN / 64, NH);
        flash_attn<<<grid, 128, FA_SMEM>>>(qkv, ctx);
    }
    // 4) output projection: [2048,2048] x [2048,2048]^T -> [2048,2048]
    {
        dim3 grid(CTX_N / 128, S_LEN / 128);
        gemm_tn<<<grid, 256>>>(ctx, w_o, out, S_LEN, CTX_N, CTX_N);
    }
}

// round 3
// speedup vs baseline: 3.6388x; 3.6388x over previous
#include <cuda_runtime.h>
#include <math.h>
#include <stdint.h>

#define S_LEN 2048
#define HID   2048
#define NH    32
#define NKV   8
#define HD    64
#define QKV_N 3072          // 2048 q + 512 k + 512 v
#define CTX_N 2048
#define K_OFF 2048
#define V_OFF 2560

// scratch (no cudaMalloc allowed)
__device__ float g_qkv[S_LEN * QKV_N];   // 25.2 MB
__device__ float g_ctx[S_LEN * CTX_N];   // 16.8 MB

__device__ __forceinline__ float f2tf(float x) {
    unsigned u;
    asm("cvt.rna.tf32.f32 %0, %1;" : "=r"(u) : "f"(x));
    return __uint_as_float(u);
}

__device__ __forceinline__ void mma_tf32(float& d0, float& d1, float& d2, float& d3,
                                         float a0, float a1, float a2, float a3,
                                         float b0, float b1) {
    asm volatile(
        "mma.sync.aligned.m16n8k8.row.col.f32.tf32.tf32.f32 "
        "{%0,%1,%2,%3}, {%4,%5,%6,%7}, {%8,%9}, {%0,%1,%2,%3};\n"
        : "+f"(d0), "+f"(d1), "+f"(d2), "+f"(d3)
        : "r"(__float_as_uint(a0)), "r"(__float_as_uint(a1)),
          "r"(__float_as_uint(a2)), "r"(__float_as_uint(a3)),
          "r"(__float_as_uint(b0)), "r"(__float_as_uint(b1)));
}

// ---------------------------------------------------------------------------
// C[m][n] = sum_k A[m][k]*B[n][k].  tf32 tensor-core GEMM.
// 128x128x32 block, 256 threads = 8 warps in 2(m) x 4(n); warp tile 64x32.
// ---------------------------------------------------------------------------
#define GPAD 36
__global__ __launch_bounds__(256, 1) void gemm_tn_mma(const float* __restrict__ A,
                                                      const float* __restrict__ B,
                                                      float* __restrict__ C,
                                                      int M, int N, int K) {
    __shared__ float As[128][GPAD];
    __shared__ float Bs[128][GPAD];
    const int tid  = threadIdx.x;
    const int warp = tid >> 5;
    const int lane = tid & 31;
    const int gid  = lane >> 2;
    const int tg   = lane & 3;
    const int wm   = warp & 1;   // 0,1 -> 64 rows each
    const int wn   = warp >> 1;  // 0..3 -> 32 cols each
    const int m0 = blockIdx.y * 128;
    const int n0 = blockIdx.x * 128;
    const int lr = tid >> 3;        // 0..31
    const int lc = (tid & 7) << 2;  // 0..28

    float acc[4][4][4];
#pragma unroll
    for (int mt = 0; mt < 4; mt++)
#pragma unroll
        for (int nt = 0; nt < 4; nt++)
#pragma unroll
            for (int i = 0; i < 4; i++) acc[mt][nt][i] = 0.0f;

    for (int kk = 0; kk < K; kk += 32) {
        float4 av[4], bv[4];
#pragma unroll
        for (int i = 0; i < 4; i++) {
            av[i] = *(const float4*)&A[(long)(m0 + lr + 32 * i) * K + kk + lc];
            bv[i] = *(const float4*)&B[(long)(n0 + lr + 32 * i) * K + kk + lc];
        }
        __syncthreads();
#pragma unroll
        for (int i = 0; i < 4; i++) {
            float4 t = av[i];
            t.x = f2tf(t.x); t.y = f2tf(t.y); t.z = f2tf(t.z); t.w = f2tf(t.w);
            *(float4*)&As[lr + 32 * i][lc] = t;
            float4 u = bv[i];
            u.x = f2tf(u.x); u.y = f2tf(u.y); u.z = f2tf(u.z); u.w = f2tf(u.w);
            *(float4*)&Bs[lr + 32 * i][lc] = u;
        }
        __syncthreads();
#pragma unroll
        for (int ks = 0; ks < 4; ks++) {
            const int k0 = ks * 8;
            float af[4][4];
#pragma unroll
            for (int mt = 0; mt < 4; mt++) {
                const int r = wm * 64 + mt * 16 + gid;
                af[mt][0] = As[r][k0 + tg];
                af[mt][1] = As[r + 8][k0 + tg];
                af[mt][2] = As[r][k0 + tg + 4];
                af[mt][3] = As[r + 8][k0 + tg + 4];
            }
#pragma unroll
            for (int nt = 0; nt < 4; nt++) {
                const int n = wn * 32 + nt * 8 + gid;
                const float b0 = Bs[n][k0 + tg];
                const float b1 = Bs[n][k0 + tg + 4];
#pragma unroll
                for (int mt = 0; mt < 4; mt++)
                    mma_tf32(acc[mt][nt][0], acc[mt][nt][1], acc[mt][nt][2], acc[mt][nt][3],
                             af[mt][0], af[mt][1], af[mt][2], af[mt][3], b0, b1);
            }
        }
    }

#pragma unroll
    for (int mt = 0; mt < 4; mt++)
#pragma unroll
        for (int nt = 0; nt < 4; nt++) {
            const int r  = m0 + wm * 64 + mt * 16 + gid;
            const int cc = n0 + wn * 32 + nt * 8 + tg * 2;
            *(float2*)&C[(long)r * N + cc]       = make_float2(acc[mt][nt][0], acc[mt][nt][1]);
            *(float2*)&C[(long)(r + 8) * N + cc] = make_float2(acc[mt][nt][2], acc[mt][nt][3]);
        }
}

// ---------------------------------------------------------------------------
// RoPE (neox) in-place on q and k.  positions = arange(S).
// Folds attention scale 1/sqrt(64)=0.125 into q.
// ---------------------------------------------------------------------------
__global__ void rope_kernel(float* __restrict__ qkv) {
    const int s  = blockIdx.x;
    const int hh = blockIdx.y;
    const int i  = threadIdx.x;
    const int base = (hh < NH) ? hh * HD : (K_OFF + (hh - NH) * HD);
    const float qs = (hh < NH) ? 0.125f : 1.0f;
    const float inv = powf(10000.0f, -(2.0f * (float)i) / 64.0f);
    const float ang = (float)s * inv;
    const float c = cosf(ang), sn = sinf(ang);
    float* row = qkv + (long)s * QKV_N + base;
    const float x1 = row[i];
    const float x2 = row[i + 32];
    row[i]      = (x1 * c - x2 * sn) * qs;
    row[i + 32] = (x2 * c + x1 * sn) * qs;
}

// ---------------------------------------------------------------------------
// Causal flash attention with tf32 mma.  64 q-rows per block, 4 warps, each
// warp owns 16 rows.  Q fragments register-resident.  V stored transposed
// (Vs[d][k]) with XOR swizzle for conflict-free transpose store + frag loads.
// ---------------------------------------------------------------------------
#define FPAD 68
// smem floats: Qs 64*68, Ks 64*68, Ps 64*68, Vs 64*64
#define FA_Q  0
#define FA_K  (64 * FPAD)
#define FA_P  (2 * 64 * FPAD)
#define FA_V  (3 * 64 * FPAD)
#define FA_SMEM ((3 * 64 * FPAD + 64 * 64) * 4)

__device__ __forceinline__ int vs_idx(int d, int k) {
    return d * 64 + (k ^ ((d & 7) << 2) ^ (d >> 3));
}

__global__ __launch_bounds__(128, 1) void flash_attn(const float* __restrict__ qkv,
                                                     float* __restrict__ ctx) {
    extern __shared__ float sm[];
    float* Qs = sm + FA_Q;   // [64][FPAD]
    float* Ks = sm + FA_K;   // [64][FPAD]
    float* Ps = sm + FA_P;   // [64][FPAD]
    float* Vs = sm + FA_V;   // swizzled [64][64]

    const int qi  = blockIdx.x;
    const int h   = blockIdx.y;
    const int kvh = h >> 2;
    const int tid  = threadIdx.x;
    const int warp = tid >> 5;
    const int lane = tid & 31;
    const int gid  = lane >> 2;
    const int tg   = lane & 3;
    const int q0   = qi * 64;
    const int woff = warp * 16;

    // ---- load Q tile, then pull fragments into registers ----
#pragma unroll
    for (int it = 0; it < 8; ++it) {
        const int f = tid + it * 128;
        const int r = f >> 4;
        const int c = (f & 15) * 4;
        float4 t = *(const float4*)&qkv[(long)(q0 + r) * QKV_N + h * HD + c];
        t.x = f2tf(t.x); t.y = f2tf(t.y); t.z = f2tf(t.z); t.w = f2tf(t.w);
        *(float4*)&Qs[r * FPAD + c] = t;
    }
    __syncthreads();
    float qa[8][4];
#pragma unroll
    for (int ks = 0; ks < 8; ks++) {
        const int r = woff + gid;
        const int k0 = ks * 8;
        qa[ks][0] = Qs[r * FPAD + k0 + tg];
        qa[ks][1] = Qs[(r + 8) * FPAD + k0 + tg];
        qa[ks][2] = Qs[r * FPAD + k0 + tg + 4];
        qa[ks][3] = Qs[(r + 8) * FPAD + k0 + tg + 4];
    }

    float acc[8][4];
#pragma unroll
    for (int dt = 0; dt < 8; dt++)
#pragma unroll
        for (int i = 0; i < 4; i++) acc[dt][i] = 0.0f;
    float m0r = -INFINITY, m1r = -INFINITY, l0r = 0.0f, l1r = 0.0f;

    for (int j = 0; j <= qi; ++j) {
        __syncthreads();
        const int k0s = j * 64;
#pragma unroll
        for (int it = 0; it < 8; ++it) {
            const int f = tid + it * 128;
            const int r = f >> 4;
            const int c = (f & 15) * 4;
            float4 t = *(const float4*)&qkv[(long)(k0s + r) * QKV_N + K_OFF + kvh * HD + c];
            t.x = f2tf(t.x); t.y = f2tf(t.y); t.z = f2tf(t.z); t.w = f2tf(t.w);
            *(float4*)&Ks[r * FPAD + c] = t;
            float4 v = *(const float4*)&qkv[(long)(k0s + r) * QKV_N + V_OFF + kvh * HD + c];
            Vs[vs_idx(c + 0, r)] = f2tf(v.x);
            Vs[vs_idx(c + 1, r)] = f2tf(v.y);
            Vs[vs_idx(c + 2, r)] = f2tf(v.z);
            Vs[vs_idx(c + 3, r)] = f2tf(v.w);
        }
        __syncthreads();

        // ---- S = Q K^T ----
        float sf[8][4];
#pragma unroll
        for (int nt = 0; nt < 8; nt++) {
#pragma unroll
            for (int i = 0; i < 4; i++) sf[nt][i] = 0.0f;
#pragma unroll
            for (int ks = 0; ks < 8; ks++) {
                const int n = nt * 8 + gid;
                const int k0 = ks * 8;
                const float b0 = Ks[n * FPAD + k0 + tg];
                const float b1 = Ks[n * FPAD + k0 + tg + 4];
                mma_tf32(sf[nt][0], sf[nt][1], sf[nt][2], sf[nt][3],
                         qa[ks][0], qa[ks][1], qa[ks][2], qa[ks][3], b0, b1);
            }
        }

        // ---- causal mask (diag block only) ----
        if (j == qi) {
            const int r0 = woff + gid;
            const int r1 = r0 + 8;
#pragma unroll
            for (int nt = 0; nt < 8; nt++) {
                const int c0 = nt * 8 + tg * 2;
                if (c0 > r0)     sf[nt][0] = -INFINITY;
                if (c0 + 1 > r0) sf[nt][1] = -INFINITY;
                if (c0 > r1)     sf[nt][2] = -INFINITY;
                if (c0 + 1 > r1) sf[nt][3] = -INFINITY;
            }
        }

        // ---- online softmax (rows r0 = woff+gid, r1 = +8) ----
        float mx0 = sf[0][0], mx1 = sf[0][2];
#pragma unroll
        for (int nt = 0; nt < 8; nt++) {
            mx0 = fmaxf(mx0, fmaxf(sf[nt][0], sf[nt][1]));
            mx1 = fmaxf(mx1, fmaxf(sf[nt][2], sf[nt][3]));
        }
        mx0 = fmaxf(mx0, __shfl_xor_sync(0xffffffffu, mx0, 1));
        mx0 = fmaxf(mx0, __shfl_xor_sync(0xffffffffu, mx0, 2));
        mx1 = fmaxf(mx1, __shfl_xor_sync(0xffffffffu, mx1, 1));
        mx1 = fmaxf(mx1, __shfl_xor_sync(0xffffffffu, mx1, 2));
        const float mn0 = fmaxf(m0r, mx0);
        const float mn1 = fmaxf(m1r, mx1);
        const float al0 = __expf(m0r - mn0);
        const float al1 = __expf(m1r - mn1);
        m0r = mn0; m1r = mn1;
        float s0 = 0.0f, s1 = 0.0f;
#pragma unroll
        for (int nt = 0; nt < 8; nt++) {
            sf[nt][0] = __expf(sf[nt][0] - mn0);
            sf[nt][1] = __expf(sf[nt][1] - mn0);
            sf[nt][2] = __expf(sf[nt][2] - mn1);
            sf[nt][3] = __expf(sf[nt][3] - mn1);
            s0 += sf[nt][0] + sf[nt][1];
            s1 += sf[nt][2] + sf[nt][3];
        }
        s0 += __shfl_xor_sync(0xffffffffu, s0, 1);
        s0 += __shfl_xor_sync(0xffffffffu, s0, 2);
        s1 += __shfl_xor_sync(0xffffffffu, s1, 1);
        s1 += __shfl_xor_sync(0xffffffffu, s1, 2);
        l0r = l0r * al0 + s0;
        l1r = l1r * al1 + s1;
#pragma unroll
        for (int dt = 0; dt < 8; dt++) {
            acc[dt][0] *= al0; acc[dt][1] *= al0;
            acc[dt][2] *= al1; acc[dt][3] *= al1;
        }

        // ---- stage P (per-warp region, warp-private) ----
#pragma unroll
        for (int nt = 0; nt < 8; nt++) {
            const int cc = nt * 8 + tg * 2;
            *(float2*)&Ps[(woff + gid) * FPAD + cc]     = make_float2(f2tf(sf[nt][0]), f2tf(sf[nt][1]));
            *(float2*)&Ps[(woff + gid + 8) * FPAD + cc] = make_float2(f2tf(sf[nt][2]), f2tf(sf[nt][3]));
        }
        __syncwarp();

        // ---- O += P V ----
#pragma unroll
        for (int ks = 0; ks < 8; ks++) {
            const int k0 = ks * 8;
            const float pa0 = Ps[(woff + gid) * FPAD + k0 + tg];
            const float pa1 = Ps[(woff + gid + 8) * FPAD + k0 + tg];
            const float pa2 = Ps[(woff + gid) * FPAD + k0 + tg + 4];
            const float pa3 = Ps[(woff + gid + 8) * FPAD + k0 + tg + 4];
#pragma unroll
            for (int dt = 0; dt < 8; dt++) {
                const int d = dt * 8 + gid;
                const float b0 = Vs[vs_idx(d, k0 + tg)];
                const float b1 = Vs[vs_idx(d, k0 + tg + 4)];
                mma_tf32(acc[dt][0], acc[dt][1], acc[dt][2], acc[dt][3],
                         pa0, pa1, pa2, pa3, b0, b1);
            }
        }
        __syncwarp();
    }

    // ---- epilogue ----
    const float il0 = 1.0f / l0r;
    const float il1 = 1.0f / l1r;
#pragma unroll
    for (int dt = 0; dt < 8; dt++) {
        const int r  = q0 + woff + gid;
        const int cc = h * HD + dt * 8 + tg * 2;
        *(float2*)&ctx[(long)r * CTX_N + cc]       = make_float2(acc[dt][0] * il0, acc[dt][1] * il0);
        *(float2*)&ctx[(long)(r + 8) * CTX_N + cc] = make_float2(acc[dt][2] * il1, acc[dt][3] * il1);
    }
}

// ---------------------------------------------------------------------------
extern "C" void kernel_launch(void* const* d_in, const int* in_sizes, int n_in,
                              void* d_out, int out_size) {
    const float* hidden = (const float*)d_in[1];
    const float* w_qkv  = (const float*)d_in[2];
    const float* w_o    = (const float*)d_in[3];
    float* out = (float*)d_out;

    float* qkv;
    float* ctx;
    cudaGetSymbolAddress((void**)&qkv, g_qkv);
    cudaGetSymbolAddress((void**)&ctx, g_ctx);

    // 1) fused QKV projection
    {
        dim3 grid(QKV_N / 128, S_LEN / 128);
        gemm_tn_mma<<<grid, 256>>>(hidden, w_qkv, qkv, S_LEN, QKV_N, HID);
    }
    // 2) RoPE on q,k (scale folded into q)
    {
        dim3 grid(S_LEN, NH + NKV);
        rope_kernel<<<grid, 32>>>(qkv);
    }
    // 3) causal flash attention (GQA, tf32 mma)
    {
        cudaFuncSetAttribute(flash_attn, cudaFuncAttributeMaxDynamicSharedMemorySize, FA_SMEM);
        dim3 grid(S_LEN / 64, NH);
        flash_attn<<<grid, 128, FA_SMEM>>>(qkv, ctx);
    }
    // 4) output projection
    {
        dim3 grid(CTX_N / 128, S_LEN / 128);
        gemm_tn_mma<<<grid, 256>>>(ctx, w_o, out, S_LEN, CTX_N, CTX_N);
    }
}

// round 4
// speedup vs baseline: 9.5803x; 2.6328x over previous
#include <cuda_runtime.h>
#include <cuda_fp16.h>
#include <math.h>
#include <stdint.h>

#define S_LEN 2048
#define HID   2048
#define NH    32
#define NKV   8
#define HD    64
#define QKV_N 3072
#define CTX_N 2048
#define K_OFF 2048
#define V_OFF 2560

// scratch (no cudaMalloc allowed)
__device__ __half g_h16 [S_LEN * HID];     // hidden fp16
__device__ __half g_wq16[QKV_N * HID];     // w_qkv fp16
__device__ __half g_wo16[HID * CTX_N];     // w_o fp16
__device__ __half g_qkv [S_LEN * QKV_N];   // qkv fp16
__device__ __half g_ctx [S_LEN * CTX_N];   // ctx fp16

// ---------------------------------------------------------------------------
__device__ __forceinline__ unsigned sptr(const void* p) {
    return (unsigned)__cvta_generic_to_shared(p);
}
#define CP_ASYNC16(dst, src) \
    asm volatile("cp.async.cg.shared.global [%0], [%1], 16;\n" :: "r"(dst), "l"(src))
#define CP_COMMIT() asm volatile("cp.async.commit_group;\n")
#define CP_WAIT0()  asm volatile("cp.async.wait_group 0;\n")

__device__ __forceinline__ void ldm_x4(unsigned& r0, unsigned& r1, unsigned& r2, unsigned& r3,
                                       unsigned addr) {
    asm volatile("ldmatrix.sync.aligned.m8n8.x4.shared.b16 {%0,%1,%2,%3}, [%4];\n"
                 : "=r"(r0), "=r"(r1), "=r"(r2), "=r"(r3) : "r"(addr));
}
__device__ __forceinline__ void ldm_x4t(unsigned& r0, unsigned& r1, unsigned& r2, unsigned& r3,
                                        unsigned addr) {
    asm volatile("ldmatrix.sync.aligned.m8n8.x4.trans.shared.b16 {%0,%1,%2,%3}, [%4];\n"
                 : "=r"(r0), "=r"(r1), "=r"(r2), "=r"(r3) : "r"(addr));
}
__device__ __forceinline__ void mma16816(float d[4], const unsigned a[4],
                                         unsigned b0, unsigned b1) {
    asm volatile("mma.sync.aligned.m16n8k16.row.col.f32.f16.f16.f32 "
                 "{%0,%1,%2,%3}, {%4,%5,%6,%7}, {%8,%9}, {%0,%1,%2,%3};\n"
                 : "+f"(d[0]), "+f"(d[1]), "+f"(d[2]), "+f"(d[3])
                 : "r"(a[0]), "r"(a[1]), "r"(a[2]), "r"(a[3]), "r"(b0), "r"(b1));
}
__device__ __forceinline__ unsigned packh2(float x, float y) {
    __half2 h = __floats2half2_rn(x, y);
    return *reinterpret_cast<unsigned*>(&h);
}

// ---------------------------------------------------------------------------
// fp32 -> fp16 conversion
// ---------------------------------------------------------------------------
__global__ void f2h(const float4* __restrict__ src, __half2* __restrict__ dst, int n4) {
    const int i = blockIdx.x * 256 + threadIdx.x;
    if (i < n4) {
        const float4 v = src[i];
        dst[2 * i]     = __floats2half2_rn(v.x, v.y);
        dst[2 * i + 1] = __floats2half2_rn(v.z, v.w);
    }
}

// ---------------------------------------------------------------------------
// C[m][n] = sum_k A[m][k]*B[n][k], fp16 in / fp32 acc.  128x128x32 tiles,
// 256 thr = 8 warps (2m x 4n), cp.async double buffer, ldmatrix fragments.
// smem layout per tile: [128 rows][32 halves], 16B-chunk swizzle c^((r>>1)&3).
// ---------------------------------------------------------------------------
template <bool HALF_OUT>
__global__ __launch_bounds__(256, 2) void gemm_tn_h(const __half* __restrict__ A,
                                                    const __half* __restrict__ B,
                                                    void* __restrict__ Cv,
                                                    int M, int N, int K) {
    __shared__ __half As[2][128 * 32];
    __shared__ __half Bs[2][128 * 32];
    const int tid  = threadIdx.x;
    const int warp = tid >> 5, lane = tid & 31;
    const int gid  = lane >> 2, tg = lane & 3;
    const int wm   = warp & 1,  wn = warp >> 1;
    const int m0 = blockIdx.y * 128, n0 = blockIdx.x * 128;

    // cp.async mapping: chunk f in [0,512): row=f>>2, c=f&3
    const int r0 = tid >> 2,         c0 = tid & 3;
    const int r1 = (tid + 256) >> 2; // c same
    const int sw0 = r0 * 32 + ((c0 ^ ((r0 >> 1) & 3)) << 3);
    const int sw1 = r1 * 32 + ((c0 ^ ((r1 >> 1) & 3)) << 3);
    const int ga0 = (m0 + r0) * K + c0 * 8;
    const int ga1 = (m0 + r1) * K + c0 * 8;
    const int gb0 = (n0 + r0) * K + c0 * 8;
    const int gb1 = (n0 + r1) * K + c0 * 8;

    float acc[4][4][4] = {};

    CP_ASYNC16(sptr(&As[0][sw0]), A + ga0);
    CP_ASYNC16(sptr(&As[0][sw1]), A + ga1);
    CP_ASYNC16(sptr(&Bs[0][sw0]), B + gb0);
    CP_ASYNC16(sptr(&Bs[0][sw1]), B + gb1);
    CP_COMMIT();

    const int nIter = K >> 5;
    for (int it = 0; it < nIter; ++it) {
        CP_WAIT0();
        __syncthreads();
        if (it + 1 < nIter) {
            const int kk = (it + 1) << 5;
            __half* a = As[(it + 1) & 1];
            __half* b = Bs[(it + 1) & 1];
            CP_ASYNC16(sptr(a + sw0), A + ga0 + kk);
            CP_ASYNC16(sptr(a + sw1), A + ga1 + kk);
            CP_ASYNC16(sptr(b + sw0), B + gb0 + kk);
            CP_ASYNC16(sptr(b + sw1), B + gb1 + kk);
            CP_COMMIT();
        }
        const __half* a = As[it & 1];
        const __half* b = Bs[it & 1];

        // B fragments: x4 covers all 4 chunks (both k16 steps) per nt tile
        unsigned bf[4][4];
        {
            const int rb = wn * 32 + (lane & 7);
            const int cb = lane >> 3;                       // chunk 0..3
#pragma unroll
            for (int nt = 0; nt < 4; nt++) {
                const int r = rb + nt * 8;
                ldm_x4(bf[nt][0], bf[nt][1], bf[nt][2], bf[nt][3],
                       sptr(b + r * 32 + ((cb ^ ((r >> 1) & 3)) << 3)));
            }
        }
#pragma unroll
        for (int p = 0; p < 2; p++) {
            unsigned af[4][4];
            const int ra = wm * 64 + (lane & 7) + ((lane >> 3) & 1) * 8;
            const int ca = p * 2 + ((lane >> 4) & 1);
#pragma unroll
            for (int mt = 0; mt < 4; mt++) {
                const int r = ra + mt * 16;
                ldm_x4(af[mt][0], af[mt][1], af[mt][2], af[mt][3],
                       sptr(a + r * 32 + ((ca ^ ((r >> 1) & 3)) << 3)));
            }
#pragma unroll
            for (int nt = 0; nt < 4; nt++)
#pragma unroll
                for (int mt = 0; mt < 4; mt++)
                    mma16816(acc[mt][nt], af[mt], bf[nt][2 * p], bf[nt][2 * p + 1]);
        }
    }

#pragma unroll
    for (int mt = 0; mt < 4; mt++)
#pragma unroll
        for (int nt = 0; nt < 4; nt++) {
            const int r = m0 + wm * 64 + mt * 16 + gid;
            const int c = n0 + wn * 32 + nt * 8 + tg * 2;
            if (HALF_OUT) {
                __half* C = (__half*)Cv;
                *(__half2*)&C[(long)r * N + c] =
                    __floats2half2_rn(acc[mt][nt][0], acc[mt][nt][1]);
                *(__half2*)&C[(long)(r + 8) * N + c] =
                    __floats2half2_rn(acc[mt][nt][2], acc[mt][nt][3]);
            } else {
                float* C = (float*)Cv;
                *(float2*)&C[(long)r * N + c] = make_float2(acc[mt][nt][0], acc[mt][nt][1]);
                *(float2*)&C[(long)(r + 8) * N + c] = make_float2(acc[mt][nt][2], acc[mt][nt][3]);
            }
        }
}

// ---------------------------------------------------------------------------
// RoPE (neox) in-place on fp16 q,k.  positions = arange(S).  Folds 1/sqrt(64)
// into q.
// ---------------------------------------------------------------------------
__global__ void rope_h(__half* __restrict__ qkv) {
    const int s  = blockIdx.x;
    const int hh = blockIdx.y;
    const int i  = threadIdx.x;
    const int base = (hh < NH) ? hh * HD : (K_OFF + (hh - NH) * HD);
    const float qs = (hh < NH) ? 0.125f : 1.0f;
    const float inv = powf(10000.0f, -(2.0f * (float)i) / 64.0f);
    const float ang = (float)s * inv;
    const float c = cosf(ang), sn = sinf(ang);
    __half* row = qkv + (long)s * QKV_N + base;
    const float x1 = __half2float(row[i]);
    const float x2 = __half2float(row[i + 32]);
    row[i]      = __float2half_rn((x1 * c - x2 * sn) * qs);
    row[i + 32] = __float2half_rn((x2 * c + x1 * sn) * qs);
}

// ---------------------------------------------------------------------------
// Causal flash attention, fp16 mma.  64 q-rows/block, 4 warps (16 rows each).
// K/V double-buffered via cp.async; V via ldmatrix.x4.trans; P stays in regs.
// smem tile layout: [64 rows][64 halves], chunk swizzle c^(r&7).
// ---------------------------------------------------------------------------
__global__ __launch_bounds__(128, 3) void flash_attn_h(const __half* __restrict__ qkv,
                                                       __half* __restrict__ ctx) {
    __shared__ __half Qs[64 * 64];
    __shared__ __half Ks[2][64 * 64];
    __shared__ __half Vs[2][64 * 64];

    const int qi  = (S_LEN / 64 - 1) - blockIdx.x;   // longest tiles first
    const int h   = blockIdx.y;
    const int kvh = h >> 2;
    const int tid = threadIdx.x, warp = tid >> 5, lane = tid & 31;
    const int gid = lane >> 2, tg = lane & 3;
    const int q0 = qi * 64, woff = warp * 16;

    // cp.async mapping: 512 chunks, 4 per thread
    int rr[4], cc8[4], sw[4];
#pragma unroll
    for (int i = 0; i < 4; i++) {
        const int f = tid + i * 128;
        const int r = f >> 3, c = f & 7;
        rr[i] = r; cc8[i] = c * 8;
        sw[i] = r * 64 + ((c ^ (r & 7)) << 3);
    }

    // prologue: Q tile + KV tile 0
#pragma unroll
    for (int i = 0; i < 4; i++)
        CP_ASYNC16(sptr(Qs + sw[i]), qkv + (q0 + rr[i]) * QKV_N + h * HD + cc8[i]);
    CP_COMMIT();
#pragma unroll
    for (int i = 0; i < 4; i++) {
        CP_ASYNC16(sptr(&Ks[0][sw[i]]), qkv + rr[i] * QKV_N + K_OFF + kvh * HD + cc8[i]);
        CP_ASYNC16(sptr(&Vs[0][sw[i]]), qkv + rr[i] * QKV_N + V_OFF + kvh * HD + cc8[i]);
    }
    CP_COMMIT();
    CP_WAIT0();
    __syncthreads();

    // Q fragments -> registers
    unsigned qa[4][4];
    {
        const int r = woff + (lane & 7) + ((lane >> 3) & 1) * 8;
        const int cb = (lane >> 4) & 1;
#pragma unroll
        for (int ks = 0; ks < 4; ks++) {
            const int c = 2 * ks + cb;
            ldm_x4(qa[ks][0], qa[ks][1], qa[ks][2], qa[ks][3],
                   sptr(Qs + r * 64 + ((c ^ (r & 7)) << 3)));
        }
    }

    float acc[8][4] = {};
    float m0r = -INFINITY, m1r = -INFINITY, l0r = 0.0f, l1r = 0.0f;

    for (int j = 0; j <= qi; ++j) {
        CP_WAIT0();
        __syncthreads();
        if (j < qi) {
            const int kb = (j + 1) * 64;
            __half* kd = Ks[(j + 1) & 1];
            __half* vd = Vs[(j + 1) & 1];
#pragma unroll
            for (int i = 0; i < 4; i++) {
                CP_ASYNC16(sptr(kd + sw[i]), qkv + (kb + rr[i]) * QKV_N + K_OFF + kvh * HD + cc8[i]);
                CP_ASYNC16(sptr(vd + sw[i]), qkv + (kb + rr[i]) * QKV_N + V_OFF + kvh * HD + cc8[i]);
            }
            CP_COMMIT();
        }
        const __half* ksm = Ks[j & 1];
        const __half* vsm = Vs[j & 1];

        // ---- S = Q K^T ----
        float sf[8][4] = {};
#pragma unroll
        for (int p = 0; p < 2; p++) {
            const int rb = lane & 7;
            const int cb = 4 * p + (lane >> 3);
#pragma unroll
            for (int nt = 0; nt < 8; nt++) {
                unsigned kb[4];
                const int r = nt * 8 + rb;
                ldm_x4(kb[0], kb[1], kb[2], kb[3],
                       sptr(ksm + r * 64 + ((cb ^ (r & 7)) << 3)));
                mma16816(sf[nt], qa[2 * p],     kb[0], kb[1]);
                mma16816(sf[nt], qa[2 * p + 1], kb[2], kb[3]);
            }
        }

        // ---- causal mask (diag block only) ----
        if (j == qi) {
            const int r0m = woff + gid;
            const int r1m = r0m + 8;
#pragma unroll
            for (int nt = 0; nt < 8; nt++) {
                const int c0 = nt * 8 + tg * 2;
                if (c0 > r0m)     sf[nt][0] = -INFINITY;
                if (c0 + 1 > r0m) sf[nt][1] = -INFINITY;
                if (c0 > r1m)     sf[nt][2] = -INFINITY;
                if (c0 + 1 > r1m) sf[nt][3] = -INFINITY;
            }
        }

        // ---- online softmax ----
        float mx0 = sf[0][0], mx1 = sf[0][2];
#pragma unroll
        for (int nt = 0; nt < 8; nt++) {
            mx0 = fmaxf(mx0, fmaxf(sf[nt][0], sf[nt][1]));
            mx1 = fmaxf(mx1, fmaxf(sf[nt][2], sf[nt][3]));
        }
        mx0 = fmaxf(mx0, __shfl_xor_sync(0xffffffffu, mx0, 1));
        mx0 = fmaxf(mx0, __shfl_xor_sync(0xffffffffu, mx0, 2));
        mx1 = fmaxf(mx1, __shfl_xor_sync(0xffffffffu, mx1, 1));
        mx1 = fmaxf(mx1, __shfl_xor_sync(0xffffffffu, mx1, 2));
        const float mn0 = fmaxf(m0r, mx0);
        const float mn1 = fmaxf(m1r, mx1);
        const float al0 = __expf(m0r - mn0);
        const float al1 = __expf(m1r - mn1);
        m0r = mn0; m1r = mn1;
        float s0 = 0.0f, s1 = 0.0f;
#pragma unroll
        for (int nt = 0; nt < 8; nt++) {
            sf[nt][0] = __expf(sf[nt][0] - mn0);
            sf[nt][1] = __expf(sf[nt][1] - mn0);
            sf[nt][2] = __expf(sf[nt][2] - mn1);
            sf[nt][3] = __expf(sf[nt][3] - mn1);
            s0 += sf[nt][0] + sf[nt][1];
            s1 += sf[nt][2] + sf[nt][3];
        }
        s0 += __shfl_xor_sync(0xffffffffu, s0, 1);
        s0 += __shfl_xor_sync(0xffffffffu, s0, 2);
        s1 += __shfl_xor_sync(0xffffffffu, s1, 1);
        s1 += __shfl_xor_sync(0xffffffffu, s1, 2);
        l0r = l0r * al0 + s0;
        l1r = l1r * al1 + s1;
#pragma unroll
        for (int dt = 0; dt < 8; dt++) {
            acc[dt][0] *= al0; acc[dt][1] *= al0;
            acc[dt][2] *= al1; acc[dt][3] *= al1;
        }

        // ---- P: C-frag -> A-frag repack (registers only) ----
        unsigned pa[4][4];
#pragma unroll
        for (int ks = 0; ks < 4; ks++) {
            pa[ks][0] = packh2(sf[2 * ks][0],     sf[2 * ks][1]);
            pa[ks][1] = packh2(sf[2 * ks][2],     sf[2 * ks][3]);
            pa[ks][2] = packh2(sf[2 * ks + 1][0], sf[2 * ks + 1][1]);
            pa[ks][3] = packh2(sf[2 * ks + 1][2], sf[2 * ks + 1][3]);
        }

        // ---- O += P V  (V via ldmatrix.trans) ----
#pragma unroll
        for (int p = 0; p < 2; p++) {
            const int r = 32 * p + (lane & 7) + (lane >> 3) * 8;
#pragma unroll
            for (int dt = 0; dt < 8; dt++) {
                unsigned vb[4];
                ldm_x4t(vb[0], vb[1], vb[2], vb[3],
                        sptr(vsm + r * 64 + ((dt ^ (r & 7)) << 3)));
                mma16816(acc[dt], pa[2 * p],     vb[0], vb[1]);
                mma16816(acc[dt], pa[2 * p + 1], vb[2], vb[3]);
            }
        }
    }

    // ---- epilogue ----
    const float il0 = 1.0f / l0r;
    const float il1 = 1.0f / l1r;
#pragma unroll
    for (int dt = 0; dt < 8; dt++) {
        const int r = q0 + woff + gid;
        const int c = h * HD + dt * 8 + tg * 2;
        *(__half2*)&ctx[(long)r * CTX_N + c] =
            __floats2half2_rn(acc[dt][0] * il0, acc[dt][1] * il0);
        *(__half2*)&ctx[(long)(r + 8) * CTX_N + c] =
            __floats2half2_rn(acc[dt][2] * il1, acc[dt][3] * il1);
    }
}

// ---------------------------------------------------------------------------
extern "C" void kernel_launch(void* const* d_in, const int* in_sizes, int n_in,
                              void* d_out, int out_size) {
    const float* hidden = (const float*)d_in[1];
    const float* w_qkv  = (const float*)d_in[2];
    const float* w_o    = (const float*)d_in[3];
    float* out = (float*)d_out;

    __half *h16, *wq16, *wo16, *qkv, *ctx;
    cudaGetSymbolAddress((void**)&h16,  g_h16);
    cudaGetSymbolAddress((void**)&wq16, g_wq16);
    cudaGetSymbolAddress((void**)&wo16, g_wo16);
    cudaGetSymbolAddress((void**)&qkv,  g_qkv);
    cudaGetSymbolAddress((void**)&ctx,  g_ctx);

    // 0) fp32 -> fp16 conversions
    f2h<<<(S_LEN * HID / 4 + 255) / 256, 256>>>((const float4*)hidden, (__half2*)h16, S_LEN * HID / 4);
    f2h<<<(QKV_N * HID / 4 + 255) / 256, 256>>>((const float4*)w_qkv, (__half2*)wq16, QKV_N * HID / 4);
    f2h<<<(HID * CTX_N / 4 + 255) / 256, 256>>>((const float4*)w_o, (__half2*)wo16, HID * CTX_N / 4);

    // 1) fused QKV projection -> fp16
    gemm_tn_h<true><<<dim3(QKV_N / 128, S_LEN / 128), 256>>>(h16, wq16, qkv, S_LEN, QKV_N, HID);
    // 2) RoPE (scale folded into q)
    rope_h<<<dim3(S_LEN, NH + NKV), 32>>>(qkv);
    // 3) causal flash attention (GQA)
    flash_attn_h<<<dim3(S_LEN / 64, NH), 128>>>(qkv, ctx);
    // 4) output projection -> fp32
    gemm_tn_h<false><<<dim3(CTX_N / 128, S_LEN / 128), 256>>>(ctx, wo16, out, S_LEN, CTX_N, CTX_N);
}

// round 8
// speedup vs baseline: 9.7809x; 1.0209x over previous
#include <cuda_runtime.h>
#include <cuda_fp16.h>
#include <math.h>
#include <stdint.h>

#define S_LEN 2048
#define HID   2048
#define NH    32
#define NKV   8
#define HD    64
#define QKV_N 3072
#define CTX_N 2048
#define K_OFF 2048
#define V_OFF 2560

// scratch (no cudaMalloc allowed)
__device__ __half g_h16 [S_LEN * HID];
__device__ __half g_wq16[QKV_N * HID];
__device__ __half g_wo16[HID * CTX_N];
__device__ __half g_qkv [S_LEN * QKV_N];
__device__ __half g_ctx [S_LEN * CTX_N];

// ---------------------------------------------------------------------------
__device__ __forceinline__ unsigned sptr(const void* p) {
    return (unsigned)__cvta_generic_to_shared(p);
}
#define CP_ASYNC16(dst, src) \
    asm volatile("cp.async.cg.shared.global [%0], [%1], 16;\n" :: "r"(dst), "l"(src))
#define CP_COMMIT() asm volatile("cp.async.commit_group;\n")
#define CP_WAIT0()  asm volatile("cp.async.wait_group 0;\n")
#define CP_WAIT1()  asm volatile("cp.async.wait_group 1;\n")
#define CP_WAIT2()  asm volatile("cp.async.wait_group 2;\n")

__device__ __forceinline__ void ldm_x4(unsigned& r0, unsigned& r1, unsigned& r2, unsigned& r3,
                                       unsigned addr) {
    asm volatile("ldmatrix.sync.aligned.m8n8.x4.shared.b16 {%0,%1,%2,%3}, [%4];\n"
                 : "=r"(r0), "=r"(r1), "=r"(r2), "=r"(r3) : "r"(addr));
}
__device__ __forceinline__ void ldm_x4t(unsigned& r0, unsigned& r1, unsigned& r2, unsigned& r3,
                                        unsigned addr) {
    asm volatile("ldmatrix.sync.aligned.m8n8.x4.trans.shared.b16 {%0,%1,%2,%3}, [%4];\n"
                 : "=r"(r0), "=r"(r1), "=r"(r2), "=r"(r3) : "r"(addr));
}
__device__ __forceinline__ void mma16816(float d[4], const unsigned a[4],
                                         unsigned b0, unsigned b1) {
    asm volatile("mma.sync.aligned.m16n8k16.row.col.f32.f16.f16.f32 "
                 "{%0,%1,%2,%3}, {%4,%5,%6,%7}, {%8,%9}, {%0,%1,%2,%3};\n"
                 : "+f"(d[0]), "+f"(d[1]), "+f"(d[2]), "+f"(d[3])
                 : "r"(a[0]), "r"(a[1]), "r"(a[2]), "r"(a[3]), "r"(b0), "r"(b1));
}
__device__ __forceinline__ unsigned packh2(float x, float y) {
    __half2 h = __floats2half2_rn(x, y);
    return *reinterpret_cast<unsigned*>(&h);
}

// ---------------------------------------------------------------------------
// fp32 -> fp16 conversion
// ---------------------------------------------------------------------------
__global__ void f2h(const float4* __restrict__ src, __half2* __restrict__ dst, int n4) {
    const int i = blockIdx.x * 256 + threadIdx.x;
    if (i < n4) {
        const float4 v = src[i];
        dst[2 * i]     = __floats2half2_rn(v.x, v.y);
        dst[2 * i + 1] = __floats2half2_rn(v.z, v.w);
    }
}

// ---------------------------------------------------------------------------
// C[m][n] = sum_k A[m][k]*B[n][k], fp16 in / fp32 acc.  128x128x32 tiles,
// 256 thr = 8 warps (2m x 4n), 4-stage cp.async pipeline, ldmatrix frags.
// smem per stage: A[128][32] + B[128][32], chunk swizzle c^((r>>1)&3).
// ---------------------------------------------------------------------------
#define GNS 4
#define GA_H (128 * 32)
#define GSTAGE_H (2 * GA_H)
#define GEMM_SMEM (GNS * GSTAGE_H * 2)

template <bool HALF_OUT>
__global__ __launch_bounds__(256, 2) void gemm_tn_h(const __half* __restrict__ A,
                                                    const __half* __restrict__ B,
                                                    void* __restrict__ Cv,
                                                    int M, int N, int K) {
    extern __shared__ __half gsm[];
    const int tid  = threadIdx.x;
    const int warp = tid >> 5, lane = tid & 31;
    const int gid  = lane >> 2, tg = lane & 3;
    const int wm   = warp & 1,  wn = warp >> 1;
    const int m0 = blockIdx.y * 128, n0 = blockIdx.x * 128;

    const int r0 = tid >> 2,         c0 = tid & 3;
    const int r1 = (tid + 256) >> 2;
    const int sw0 = r0 * 32 + ((c0 ^ ((r0 >> 1) & 3)) << 3);
    const int sw1 = r1 * 32 + ((c0 ^ ((r1 >> 1) & 3)) << 3);
    const long ga0 = (long)(m0 + r0) * K + c0 * 8;
    const long ga1 = (long)(m0 + r1) * K + c0 * 8;
    const long gb0 = (long)(n0 + r0) * K + c0 * 8;
    const long gb1 = (long)(n0 + r1) * K + c0 * 8;

    float acc[4][4][4] = {};

#define G_LOAD(IT)                                                      \
    do {                                                                \
        const int kk_ = (IT) << 5;                                      \
        __half* a_ = gsm + ((IT) & (GNS - 1)) * GSTAGE_H;               \
        __half* b_ = a_ + GA_H;                                         \
        CP_ASYNC16(sptr(a_ + sw0), A + ga0 + kk_);                      \
        CP_ASYNC16(sptr(a_ + sw1), A + ga1 + kk_);                      \
        CP_ASYNC16(sptr(b_ + sw0), B + gb0 + kk_);                      \
        CP_ASYNC16(sptr(b_ + sw1), B + gb1 + kk_);                      \
        CP_COMMIT();                                                    \
    } while (0)

    const int nIter = K >> 5;
    G_LOAD(0); G_LOAD(1); G_LOAD(2);

    for (int it = 0; it < nIter; ++it) {
        if (it + 3 <= nIter)      { CP_WAIT2(); }
        else if (it + 2 == nIter) { CP_WAIT1(); }
        else                      { CP_WAIT0(); }
        __syncthreads();
        if (it + 3 < nIter) G_LOAD(it + 3);

        const __half* a = gsm + (it & (GNS - 1)) * GSTAGE_H;
        const __half* b = a + GA_H;

        unsigned bf[4][4];
        {
            const int rb = wn * 32 + (lane & 7);
            const int cb = lane >> 3;
#pragma unroll
            for (int nt = 0; nt < 4; nt++) {
                const int r = rb + nt * 8;
                ldm_x4(bf[nt][0], bf[nt][1], bf[nt][2], bf[nt][3],
                       sptr(b + r * 32 + ((cb ^ ((r >> 1) & 3)) << 3)));
            }
        }
#pragma unroll
        for (int p = 0; p < 2; p++) {
            unsigned af[4][4];
            const int ra = wm * 64 + (lane & 7) + ((lane >> 3) & 1) * 8;
            const int ca = p * 2 + ((lane >> 4) & 1);
#pragma unroll
            for (int mt = 0; mt < 4; mt++) {
                const int r = ra + mt * 16;
                ldm_x4(af[mt][0], af[mt][1], af[mt][2], af[mt][3],
                       sptr(a + r * 32 + ((ca ^ ((r >> 1) & 3)) << 3)));
            }
#pragma unroll
            for (int nt = 0; nt < 4; nt++)
#pragma unroll
                for (int mt = 0; mt < 4; mt++)
                    mma16816(acc[mt][nt], af[mt], bf[nt][2 * p], bf[nt][2 * p + 1]);
        }
    }

#pragma unroll
    for (int mt = 0; mt < 4; mt++)
#pragma unroll
        for (int nt = 0; nt < 4; nt++) {
            const int r = m0 + wm * 64 + mt * 16 + gid;
            const int c = n0 + wn * 32 + nt * 8 + tg * 2;
            if (HALF_OUT) {
                __half* C = (__half*)Cv;
                *(__half2*)&C[(long)r * N + c] =
                    __floats2half2_rn(acc[mt][nt][0], acc[mt][nt][1]);
                *(__half2*)&C[(long)(r + 8) * N + c] =
                    __floats2half2_rn(acc[mt][nt][2], acc[mt][nt][3]);
            } else {
                float* C = (float*)Cv;
                *(float2*)&C[(long)r * N + c] = make_float2(acc[mt][nt][0], acc[mt][nt][1]);
                *(float2*)&C[(long)(r + 8) * N + c] = make_float2(acc[mt][nt][2], acc[mt][nt][3]);
            }
        }
}

// ---------------------------------------------------------------------------
// RoPE (neox) in-place on fp16 q,k.  positions = arange(S).  Folds 1/sqrt(64)
// into q.  256 threads = 8 heads per block.
// ---------------------------------------------------------------------------
__global__ __launch_bounds__(256) void rope_h(__half* __restrict__ qkv) {
    const int s  = blockIdx.x;
    const int hh = blockIdx.y * 8 + (threadIdx.x >> 5);
    const int i  = threadIdx.x & 31;
    const int base = (hh < NH) ? hh * HD : (K_OFF + (hh - NH) * HD);
    const float qs = (hh < NH) ? 0.125f : 1.0f;
    const float inv = powf(10000.0f, -(2.0f * (float)i) / 64.0f);
    const float ang = (float)s * inv;
    const float c = cosf(ang), sn = sinf(ang);
    __half* row = qkv + (long)s * QKV_N + base;
    const float x1 = __half2float(row[i]);
    const float x2 = __half2float(row[i + 32]);
    row[i]      = __float2half_rn((x1 * c - x2 * sn) * qs);
    row[i + 32] = __float2half_rn((x2 * c + x1 * sn) * qs);
}

// ---------------------------------------------------------------------------
// Causal flash attention, fp16 mma.  128 q-rows/block, 8 warps (16 rows each),
// 3-stage K/V cp.async pipeline, V via ldmatrix.x4.trans, P stays in regs.
// smem: Q[128][64] + 3 x (K[64][64] + V[64][64]), chunk swizzle c^(r&7).
// ---------------------------------------------------------------------------
#define FQ_H (128 * 64)
#define FKV_H (64 * 64)
#define FA_SMEM ((FQ_H + 3 * 2 * FKV_H) * 2)

__global__ __launch_bounds__(256, 2) void flash_attn_h(const __half* __restrict__ qkv,
                                                       __half* __restrict__ ctx) {
    extern __shared__ __half fsm[];
    __half* Qs = fsm;   // [128][64]

    const int qt  = (S_LEN / 128 - 1) - blockIdx.x;   // longest tiles first
    const int h   = blockIdx.y;
    const int kvh = h >> 2;
    const int tid = threadIdx.x, warp = tid >> 5, lane = tid & 31;
    const int gid = lane >> 2, tg = lane & 3;
    const int q0 = qt * 128, woff = warp * 16;
    const int jmax = (q0 + 127) >> 6;

    // K/V loader mapping: 512 chunks per 64x64 tile, 2 per thread
    int rr[2], cc8[2], sw[2];
#pragma unroll
    for (int i = 0; i < 2; i++) {
        const int f = tid + i * 256;
        const int r = f >> 3, c = f & 7;
        rr[i] = r; cc8[i] = c * 8;
        sw[i] = r * 64 + ((c ^ (r & 7)) << 3);
    }

#define FA_LOADKV(J)                                                                     \
    do {                                                                                 \
        const int kb_ = (J) * 64;                                                        \
        __half* kd_ = fsm + FQ_H + ((J) % 3) * 2 * FKV_H;                                \
        __half* vd_ = kd_ + FKV_H;                                                       \
        _Pragma("unroll")                                                                \
        for (int i_ = 0; i_ < 2; i_++) {                                                 \
            CP_ASYNC16(sptr(kd_ + sw[i_]),                                               \
                       qkv + (long)(kb_ + rr[i_]) * QKV_N + K_OFF + kvh * HD + cc8[i_]); \
            CP_ASYNC16(sptr(vd_ + sw[i_]),                                               \
                       qkv + (long)(kb_ + rr[i_]) * QKV_N + V_OFF + kvh * HD + cc8[i_]); \
        }                                                                                \
        CP_COMMIT();                                                                     \
    } while (0)

    // prologue: Q (1024 chunks, 4/thread) then KV0, KV1
#pragma unroll
    for (int i = 0; i < 4; i++) {
        const int f = tid + i * 256;
        const int r = f >> 3, c = f & 7;
        CP_ASYNC16(sptr(Qs + r * 64 + ((c ^ (r & 7)) << 3)),
                   qkv + (long)(q0 + r) * QKV_N + h * HD + c * 8);
    }
    CP_COMMIT();
    FA_LOADKV(0);
    FA_LOADKV(1);

    CP_WAIT2();          // Q done (KV0, KV1 may be in flight)
    __syncthreads();

    unsigned qa[4][4];
    {
        const int r = woff + (lane & 7) + ((lane >> 3) & 1) * 8;
        const int cb = (lane >> 4) & 1;
#pragma unroll
        for (int ks = 0; ks < 4; ks++) {
            const int c = 2 * ks + cb;
            ldm_x4(qa[ks][0], qa[ks][1], qa[ks][2], qa[ks][3],
                   sptr(Qs + r * 64 + ((c ^ (r & 7)) << 3)));
        }
    }

    float acc[8][4] = {};
    float m0r = -INFINITY, m1r = -INFINITY, l0r = 0.0f, l1r = 0.0f;

    for (int j = 0; j <= jmax; ++j) {
        if (j < jmax) { CP_WAIT1(); } else { CP_WAIT0(); }
        __syncthreads();
        if (j + 2 <= jmax) FA_LOADKV(j + 2);

        // skip fully-masked iterations for this warp (still did sync+prefetch)
        if ((j << 6) > q0 + woff + 15) continue;

        const __half* ksm = fsm + FQ_H + (j % 3) * 2 * FKV_H;
        const __half* vsm = ksm + FKV_H;

        // ---- S = Q K^T ----
        float sf[8][4] = {};
#pragma unroll
        for (int p = 0; p < 2; p++) {
            const int rb = lane & 7;
            const int cb = 4 * p + (lane >> 3);
#pragma unroll
            for (int nt = 0; nt < 8; nt++) {
                unsigned kb[4];
                const int r = nt * 8 + rb;
                ldm_x4(kb[0], kb[1], kb[2], kb[3],
                       sptr(ksm + r * 64 + ((cb ^ (r & 7)) << 3)));
                mma16816(sf[nt], qa[2 * p],     kb[0], kb[1]);
                mma16816(sf[nt], qa[2 * p + 1], kb[2], kb[3]);
            }
        }

        // ---- causal mask (absolute coords; only near diagonal) ----
        if ((j << 6) + 63 > q0 + woff) {
            const int r0m = q0 + woff + gid;
            const int r1m = r0m + 8;
#pragma unroll
            for (int nt = 0; nt < 8; nt++) {
                const int c0 = (j << 6) + nt * 8 + tg * 2;
                if (c0 > r0m)     sf[nt][0] = -INFINITY;
                if (c0 + 1 > r0m) sf[nt][1] = -INFINITY;
                if (c0 > r1m)     sf[nt][2] = -INFINITY;
                if (c0 + 1 > r1m) sf[nt][3] = -INFINITY;
            }
        }

        // ---- online softmax ----
        float mx0 = sf[0][0], mx1 = sf[0][2];
#pragma unroll
        for (int nt = 0; nt < 8; nt++) {
            mx0 = fmaxf(mx0, fmaxf(sf[nt][0], sf[nt][1]));
            mx1 = fmaxf(mx1, fmaxf(sf[nt][2], sf[nt][3]));
        }
        mx0 = fmaxf(mx0, __shfl_xor_sync(0xffffffffu, mx0, 1));
        mx0 = fmaxf(mx0, __shfl_xor_sync(0xffffffffu, mx0, 2));
        mx1 = fmaxf(mx1, __shfl_xor_sync(0xffffffffu, mx1, 1));
        mx1 = fmaxf(mx1, __shfl_xor_sync(0xffffffffu, mx1, 2));
        const float mn0 = fmaxf(m0r, mx0);
        const float mn1 = fmaxf(m1r, mx1);
        const float al0 = __expf(m0r - mn0);
        const float al1 = __expf(m1r - mn1);
        m0r = mn0; m1r = mn1;
        float s0 = 0.0f, s1 = 0.0f;
#pragma unroll
        for (int nt = 0; nt < 8; nt++) {
            sf[nt][0] = __expf(sf[nt][0] - mn0);
            sf[nt][1] = __expf(sf[nt][1] - mn0);
            sf[nt][2] = __expf(sf[nt][2] - mn1);
            sf[nt][3] = __expf(sf[nt][3] - mn1);
            s0 += sf[nt][0] + sf[nt][1];
            s1 += sf[nt][2] + sf[nt][3];
        }
        s0 += __shfl_xor_sync(0xffffffffu, s0, 1);
        s0 += __shfl_xor_sync(0xffffffffu, s0, 2);
        s1 += __shfl_xor_sync(0xffffffffu, s1, 1);
        s1 += __shfl_xor_sync(0xffffffffu, s1, 2);
        l0r = l0r * al0 + s0;
        l1r = l1r * al1 + s1;
#pragma unroll
        for (int dt = 0; dt < 8; dt++) {
            acc[dt][0] *= al0; acc[dt][1] *= al0;
            acc[dt][2] *= al1; acc[dt][3] *= al1;
        }

        // ---- P: C-frag -> A-frag repack (registers only) ----
        unsigned pa[4][4];
#pragma unroll
        for (int ks = 0; ks < 4; ks++) {
            pa[ks][0] = packh2(sf[2 * ks][0],     sf[2 * ks][1]);
            pa[ks][1] = packh2(sf[2 * ks][2],     sf[2 * ks][3]);
            pa[ks][2] = packh2(sf[2 * ks + 1][0], sf[2 * ks + 1][1]);
            pa[ks][3] = packh2(sf[2 * ks + 1][2], sf[2 * ks + 1][3]);
        }

        // ---- O += P V  (V via ldmatrix.trans) ----
#pragma unroll
        for (int p = 0; p < 2; p++) {
            const int r = 32 * p + (lane & 7) + (lane >> 3) * 8;
#pragma unroll
            for (int dt = 0; dt < 8; dt++) {
                unsigned vb[4];
                ldm_x4t(vb[0], vb[1], vb[2], vb[3],
                        sptr(vsm + r * 64 + ((dt ^ (r & 7)) << 3)));
                mma16816(acc[dt], pa[2 * p],     vb[0], vb[1]);
                mma16816(acc[dt], pa[2 * p + 1], vb[2], vb[3]);
            }
        }
    }

    // ---- epilogue ----
    const float il0 = 1.0f / l0r;
    const float il1 = 1.0f / l1r;
#pragma unroll
    for (int dt = 0; dt < 8; dt++) {
        const int r = q0 + woff + gid;
        const int c = h * HD + dt * 8 + tg * 2;
        *(__half2*)&ctx[(long)r * CTX_N + c] =
            __floats2half2_rn(acc[dt][0] * il0, acc[dt][1] * il0);
        *(__half2*)&ctx[(long)(r + 8) * CTX_N + c] =
            __floats2half2_rn(acc[dt][2] * il1, acc[dt][3] * il1);
    }
}

// ---------------------------------------------------------------------------
extern "C" void kernel_launch(void* const* d_in, const int* in_sizes, int n_in,
                              void* d_out, int out_size) {
    const float* hidden = (const float*)d_in[1];
    const float* w_qkv  = (const float*)d_in[2];
    const float* w_o    = (const float*)d_in[3];
    float* out = (float*)d_out;

    __half *h16, *wq16, *wo16, *qkv, *ctx;
    cudaGetSymbolAddress((void**)&h16,  g_h16);
    cudaGetSymbolAddress((void**)&wq16, g_wq16);
    cudaGetSymbolAddress((void**)&wo16, g_wo16);
    cudaGetSymbolAddress((void**)&qkv,  g_qkv);
    cudaGetSymbolAddress((void**)&ctx,  g_ctx);

    cudaFuncSetAttribute(gemm_tn_h<true>,  cudaFuncAttributeMaxDynamicSharedMemorySize, GEMM_SMEM);
    cudaFuncSetAttribute(gemm_tn_h<false>, cudaFuncAttributeMaxDynamicSharedMemorySize, GEMM_SMEM);
    cudaFuncSetAttribute(flash_attn_h,     cudaFuncAttributeMaxDynamicSharedMemorySize, FA_SMEM);

    // 0) fp32 -> fp16 conversions
    f2h<<<(S_LEN * HID / 4 + 255) / 256, 256>>>((const float4*)hidden, (__half2*)h16, S_LEN * HID / 4);
    f2h<<<(QKV_N * HID / 4 + 255) / 256, 256>>>((const float4*)w_qkv, (__half2*)wq16, QKV_N * HID / 4);
    f2h<<<(HID * CTX_N / 4 + 255) / 256, 256>>>((const float4*)w_o, (__half2*)wo16, HID * CTX_N / 4);

    // 1) fused QKV projection -> fp16
    gemm_tn_h<true><<<dim3(QKV_N / 128, S_LEN / 128), 256, GEMM_SMEM>>>(h16, wq16, qkv, S_LEN, QKV_N, HID);
    // 2) RoPE (scale folded into q)
    rope_h<<<dim3(S_LEN, 5), 256>>>(qkv);
    // 3) causal flash attention (GQA)
    flash_attn_h<<<dim3(S_LEN / 128, NH), 256, FA_SMEM>>>(qkv, ctx);
    // 4) output projection -> fp32
    gemm_tn_h<false><<<dim3(CTX_N / 128, S_LEN / 128), 256, GEMM_SMEM>>>(ctx, wo16, out, S_LEN, CTX_N, CTX_N);
}